// round 2
// baseline (speedup 1.0000x reference)
#include <cuda_runtime.h>
#include <cuda_fp16.h>

#define NN 50000
#define NE 1600000

// Scratch (device globals; no allocation allowed).
__device__ float  g_h[NN * 128];     // projected features [N,128] fp32
__device__ __half g_h2[NN * 128];    // fp16 copy for the scatter gather
__device__ float  g_s[NN * 4];       // alpha_src per node/head
__device__ float  g_d[NN * 4];       // alpha_dst per node/head
__device__ int    g_last[NN];        // last edge index with src==n, else -1
__device__ float  g_expv[NN * 4];    // exp(leaky_relu(logit)) per valid node/head
__device__ float  g_sum[4];          // softmax denominators per head
__device__ float  g_inv[4];          // 0.25 / g_sum
__device__ float  g_alpha[NN * 4];   // packed per-node weights = expv * inv

// ---------------------------------------------------------------------------
// K1: h = x @ W + b  via packed fma.rn.f32x2 (2 FMA/instr).
// Block 256 threads -> 64 rows x 128 cols, BK=32.
// Epilogue fuses: fp32 h store, fp16 h2 store, attn s/d dot products.
// ---------------------------------------------------------------------------
__global__ __launch_bounds__(256) void gemm_h(const float* __restrict__ x,
                                              const float* __restrict__ W,
                                              const float* __restrict__ b,
                                              const float* __restrict__ asrc,
                                              const float* __restrict__ adst,
                                              int N)
{
    __shared__ float sW[32 * 128];    // 16 KB, W tile [k][col]
    __shared__ float sxD[64 * 64];    // 16 KB, x tile duplicated: [row][k] as (x,x) pairs

    const int tid  = threadIdx.x;
    const int tx   = tid & 31;        // lane: cols 4*tx .. 4*tx+3
    const int ty   = tid >> 5;        // warp: rows ty*8 .. ty*8+7
    const int row0 = blockIdx.x * 64;

    unsigned long long acc01[8];      // (col0,col1) fp32x2 accumulators per row
    unsigned long long acc23[8];      // (col2,col3)
#pragma unroll
    for (int i = 0; i < 8; i++) { acc01[i] = 0ull; acc23[i] = 0ull; }

    for (int kk = 0; kk < 128; kk += 32) {
        // W tile [32][128]
        {
            int r = tid >> 5;
            int c = (tid & 31) * 4;
#pragma unroll
            for (int i = 0; i < 4; i++) {
                int k = kk + r + 8 * i;
                float4 wv = *reinterpret_cast<const float4*>(&W[k * 128 + c]);
                *reinterpret_cast<float4*>(&sW[(r + 8 * i) * 128 + c]) = wv;
            }
        }
        // x tile [64][32] stored duplicated: sxD[row*64 + 2k] = sxD[..+1] = x[row][k]
        {
            int r = tid >> 3;
            int c = (tid & 7) * 4;
#pragma unroll
            for (int i = 0; i < 2; i++) {
                int row = row0 + r + 32 * i;
                int rr  = row < N ? row : (N - 1);
                float4 xv = *reinterpret_cast<const float4*>(&x[(size_t)rr * 128 + kk + c]);
                float4 d0 = make_float4(xv.x, xv.x, xv.y, xv.y);
                float4 d1 = make_float4(xv.z, xv.z, xv.w, xv.w);
                float* base = &sxD[(r + 32 * i) * 64 + 2 * c];
                *reinterpret_cast<float4*>(base)     = d0;
                *reinterpret_cast<float4*>(base + 4) = d1;
            }
        }
        __syncthreads();

#pragma unroll
        for (int k = 0; k < 32; k++) {
            ulonglong2 wv = *reinterpret_cast<const ulonglong2*>(&sW[k * 128 + tx * 4]);
#pragma unroll
            for (int i = 0; i < 8; i++) {
                unsigned long long xx =
                    *reinterpret_cast<const unsigned long long*>(&sxD[(ty * 8 + i) * 64 + 2 * k]);
                asm("fma.rn.f32x2 %0, %1, %2, %0;" : "+l"(acc01[i]) : "l"(wv.x), "l"(xx));
                asm("fma.rn.f32x2 %0, %1, %2, %0;" : "+l"(acc23[i]) : "l"(wv.y), "l"(xx));
            }
        }
        __syncthreads();
    }

    const float4 bv  = *reinterpret_cast<const float4*>(&b[tx * 4]);
    const float4 asv = *reinterpret_cast<const float4*>(&asrc[tx * 4]);
    const float4 adv = *reinterpret_cast<const float4*>(&adst[tx * 4]);

#pragma unroll
    for (int i = 0; i < 8; i++) {
        int row = row0 + ty * 8 + i;
        if (row < N) {
            float2 u01 = *reinterpret_cast<float2*>(&acc01[i]);
            float2 u23 = *reinterpret_cast<float2*>(&acc23[i]);
            float4 o;
            o.x = u01.x + bv.x;
            o.y = u01.y + bv.y;
            o.z = u23.x + bv.z;
            o.w = u23.y + bv.w;
            *reinterpret_cast<float4*>(&g_h[(size_t)row * 128 + tx * 4]) = o;

            // fp16 copy
            __half2 p0 = __floats2half2_rn(o.x, o.y);
            __half2 p1 = __floats2half2_rn(o.z, o.w);
            uint2 hv;
            hv.x = *reinterpret_cast<unsigned int*>(&p0);
            hv.y = *reinterpret_cast<unsigned int*>(&p1);
            *reinterpret_cast<uint2*>(&g_h2[(size_t)row * 128 + tx * 4]) = hv;

            // attn dots: reduce within 8-lane (per-head) groups
            float ps = o.x * asv.x + o.y * asv.y + o.z * asv.z + o.w * asv.w;
            float pd = o.x * adv.x + o.y * adv.y + o.z * adv.z + o.w * adv.w;
#pragma unroll
            for (int off = 4; off > 0; off >>= 1) {
                ps += __shfl_down_sync(0xffffffffu, ps, off);
                pd += __shfl_down_sync(0xffffffffu, pd, off);
            }
            if ((tx & 7) == 0) {
                int head = tx >> 3;
                g_s[row * 4 + head] = ps;
                g_d[row * 4 + head] = pd;
            }
        }
    }
}

// ---------------------------------------------------------------------------
// K2: init: out=0, last=-1, sum=0.
// ---------------------------------------------------------------------------
__global__ void init_k(float* __restrict__ out, int N)
{
    int i = blockIdx.x * blockDim.x + threadIdx.x;
    if (i < N * 32) out[i] = 0.f;
    if (i < N)      g_last[i] = -1;
    if (i < 4)      g_sum[i] = 0.f;
}

// ---------------------------------------------------------------------------
// K3: last[src[e]] = max(e). 4 edges per thread for MLP.
// ---------------------------------------------------------------------------
__global__ void last_k(const int* __restrict__ src, int E)
{
    int i = blockIdx.x * blockDim.x + threadIdx.x;
    int e0 = i * 4;
    if (e0 + 3 < E) {
        int4 s = *reinterpret_cast<const int4*>(&src[e0]);
        atomicMax(&g_last[s.x], e0);
        atomicMax(&g_last[s.y], e0 + 1);
        atomicMax(&g_last[s.z], e0 + 2);
        atomicMax(&g_last[s.w], e0 + 3);
    } else {
        for (int e = e0; e < E; e++) atomicMax(&g_last[src[e]], e);
    }
}

// ---------------------------------------------------------------------------
// K4: per-node logits -> exp, reduce denominators.
// ---------------------------------------------------------------------------
__global__ __launch_bounds__(256) void alpha_k(const int* __restrict__ dstI,
                                               const float* __restrict__ eattr,
                                               const float* __restrict__ eW1,
                                               const float* __restrict__ eb1,
                                               const float* __restrict__ eW2,
                                               const float* __restrict__ eb2,
                                               int N)
{
    int n = blockIdx.x * blockDim.x + threadIdx.x;
    float ev[4] = {0.f, 0.f, 0.f, 0.f};
    if (n < N) {
        int e = g_last[n];
        if (e >= 0) {
            int m = dstI[e];
            float4 ea = *reinterpret_cast<const float4*>(&eattr[(size_t)e * 4]);
            float vh0 = eb2[0], vh1 = eb2[1], vh2 = eb2[2], vh3 = eb2[3];
#pragma unroll
            for (int j = 0; j < 32; j++) {
                float hid = ea.x * eW1[j] + ea.y * eW1[32 + j] +
                            ea.z * eW1[64 + j] + ea.w * eW1[96 + j] + eb1[j];
                hid = fmaxf(hid, 0.f);
                vh0 += hid * eW2[j * 4 + 0];
                vh1 += hid * eW2[j * 4 + 1];
                vh2 += hid * eW2[j * 4 + 2];
                vh3 += hid * eW2[j * 4 + 3];
            }
            float vh[4] = {vh0, vh1, vh2, vh3};
#pragma unroll
            for (int hh = 0; hh < 4; hh++) {
                float v = g_s[n * 4 + hh] + g_d[m * 4 + hh] + vh[hh];
                v = v > 0.f ? v : 0.2f * v;           // leaky_relu(0.2)
                float xv = expf(v);
                ev[hh] = xv;
                g_expv[n * 4 + hh] = xv;
            }
        }
    }
#pragma unroll
    for (int hh = 0; hh < 4; hh++) {
        float t = ev[hh];
#pragma unroll
        for (int o = 16; o > 0; o >>= 1) t += __shfl_down_sync(0xffffffffu, t, o);
        if ((threadIdx.x & 31) == 0) atomicAdd(&g_sum[hh], t);
    }
}

// ---------------------------------------------------------------------------
// K5: inv[h] = 0.25 / sum[h]   (0.25 = head-mean folded in)
// ---------------------------------------------------------------------------
__global__ void finalize_k()
{
    int h = threadIdx.x;
    if (h < 4) g_inv[h] = 0.25f / g_sum[h];
}

// ---------------------------------------------------------------------------
// K6: pack alpha per node: g_alpha[n,h] = expv[n,h] * inv[h]
// ---------------------------------------------------------------------------
__global__ void pack_k(int N)
{
    int i = blockIdx.x * blockDim.x + threadIdx.x;
    if (i < N * 4) g_alpha[i] = g_expv[i] * g_inv[i & 3];
}

// ---------------------------------------------------------------------------
// K7: scatter. One warp per edge: out[src, f] += sum_h a_h * h2[dst, h*32+f].
// ---------------------------------------------------------------------------
__global__ __launch_bounds__(256) void scatter_k(const int* __restrict__ src,
                                                 const int* __restrict__ dstI,
                                                 float* __restrict__ out,
                                                 int E)
{
    int gw   = (blockIdx.x * 256 + threadIdx.x) >> 5;
    int lane = threadIdx.x & 31;
    if (gw >= E) return;

    int n = __ldg(&src[gw]);
    int m = __ldg(&dstI[gw]);

    float4 a = *reinterpret_cast<const float4*>(&g_alpha[n * 4]);  // uniform -> broadcast

    const __half* hp = g_h2 + (size_t)m * 128;
    float c = a.x * __half2float(__ldg(&hp[lane])) +
              a.y * __half2float(__ldg(&hp[32 + lane])) +
              a.z * __half2float(__ldg(&hp[64 + lane])) +
              a.w * __half2float(__ldg(&hp[96 + lane]));

    atomicAdd(&out[(size_t)n * 32 + lane], c);
}

// ---------------------------------------------------------------------------
extern "C" void kernel_launch(void* const* d_in, const int* in_sizes, int n_in,
                              void* d_out, int out_size)
{
    const float* x    = (const float*)d_in[0];
    const int*   ei   = (const int*)d_in[1];
    const float* ea   = (const float*)d_in[2];
    const float* W    = (const float*)d_in[3];
    const float* b    = (const float*)d_in[4];
    const float* eW1  = (const float*)d_in[5];
    const float* eb1  = (const float*)d_in[6];
    const float* eW2  = (const float*)d_in[7];
    const float* eb2  = (const float*)d_in[8];
    const float* asrc = (const float*)d_in[9];
    const float* adst = (const float*)d_in[10];
    float* out = (float*)d_out;

    int N = in_sizes[0] / 128;
    int E = in_sizes[1] / 2;
    const int* srcI = ei;
    const int* dstI = ei + E;

    gemm_h<<<(N + 63) / 64, 256>>>(x, W, b, asrc, adst, N);
    init_k<<<(N * 32 + 255) / 256, 256>>>(out, N);
    last_k<<<((E + 3) / 4 + 255) / 256, 256>>>(srcI, E);
    alpha_k<<<(N + 255) / 256, 256>>>(dstI, ea, eW1, eb1, eW2, eb2, N);
    finalize_k<<<1, 32>>>();
    pack_k<<<(N * 4 + 255) / 256, 256>>>(N);
    scatter_k<<<(E + 7) / 8, 256>>>(srcI, dstI, out, E);
}